// round 4
// baseline (speedup 1.0000x reference)
#include <cuda_runtime.h>
#include <cstdint>

#define B 4
#define L 2048
#define H 8
#define D 64
#define NT 38           // n_top
#define SK 38           // sample_k
#define NIDX (L*SK)     // 77824
#define CH 16           // cumsum chunks
#define CROWS (L/CH)    // 128 rows per chunk
#define KC 64           // attention key-chunk
#define NC (L/KC)       // 32 chunks

// ---------------- scratch (no allocations allowed) ----------------
__device__ int   g_idx[NIDX];          // index_sample, row-major (q, j)
__device__ float g_M[B*H*L];           // sparsity metric
__device__ int   g_top[B*H*NT];        // selected query indices per (b,h)
__device__ float g_csum[B*H*CH*D];     // per-chunk column sums
__device__ float g_pm[B*H*NT*NC];      // attention partial max
__device__ float g_pl[B*H*NT*NC];      // attention partial sum
__device__ float g_pacc[B*H*NT*NC*D];  // attention partial weighted V

// ---------------- threefry2x32-20 (jax partitionable path) ----------------
__device__ __forceinline__ uint32_t rotl32(uint32_t x, int r) {
    return (x << r) | (x >> (32 - r));
}

__device__ __forceinline__ void threefry2x32(uint32_t k0, uint32_t k1,
                                             uint32_t x0, uint32_t x1,
                                             uint32_t& o0, uint32_t& o1) {
    uint32_t ks2 = k0 ^ k1 ^ 0x1BD11BDAu;
    x0 += k0; x1 += k1;
#define TF_R(R) { x0 += x1; x1 = rotl32(x1, (R)); x1 ^= x0; }
    TF_R(13) TF_R(15) TF_R(26) TF_R(6)
    x0 += k1;  x1 += ks2 + 1u;
    TF_R(17) TF_R(29) TF_R(16) TF_R(24)
    x0 += ks2; x1 += k0 + 2u;
    TF_R(13) TF_R(15) TF_R(26) TF_R(6)
    x0 += k0;  x1 += k1 + 3u;
    TF_R(17) TF_R(29) TF_R(16) TF_R(24)
    x0 += k1;  x1 += ks2 + 4u;
    TF_R(13) TF_R(15) TF_R(26) TF_R(6)
    x0 += ks2; x1 += k0 + 5u;
#undef TF_R
    o0 = x0; o1 = x1;
}

__global__ void k_genidx() {
    int t = blockIdx.x * blockDim.x + threadIdx.x;
    if (t >= NIDX) return;
    uint32_t c0, c1;
    threefry2x32(0u, 42u, 0u, 1u, c0, c1);   // lower key (constant-folds)
    uint32_t o0, o1;
    threefry2x32(c0, c1, 0u, (uint32_t)t, o0, o1);
    g_idx[t] = (int)((o0 ^ o1) & (uint32_t)(L - 1));
}

// ---------------- M metric: warp per query, 4 samples per iteration ----------------
__global__ void k_M(const float* __restrict__ Q, const float* __restrict__ K) {
    int bh = blockIdx.x;
    int b = bh >> 3, h = bh & 7;
    int w = threadIdx.x >> 5, l = threadIdx.x & 31;
    int q = blockIdx.y * 8 + w;
    int s = l >> 3, c = l & 7;

    const float4* qr = (const float4*)(Q + (((size_t)b * L + q) * H + h) * D);
    float4 qa = qr[2 * c], qb = qr[2 * c + 1];
    const float4* Kb = (const float4*)(K + (((size_t)b * L) * H + h) * D);

    float mx = -1e30f, sm = 0.f;
    const int* ip = &g_idx[q * SK];
    #pragma unroll 2
    for (int j0 = 0; j0 < 40; j0 += 4) {
        int j = j0 + s;
        int jc = min(j, SK - 1);
        int k = ip[jc];
        const float4* kr = Kb + (size_t)k * (H * D / 4) + 2 * c;
        float4 ka = kr[0], kb = kr[1];
        float p = ka.x * qa.x + ka.y * qa.y + ka.z * qa.z + ka.w * qa.w
                + kb.x * qb.x + kb.y * qb.y + kb.z * qb.z + kb.w * qb.w;
        p += __shfl_xor_sync(0xffffffffu, p, 1);
        p += __shfl_xor_sync(0xffffffffu, p, 2);
        p += __shfl_xor_sync(0xffffffffu, p, 4);
        bool valid = (j < SK);
        mx = fmaxf(mx, valid ? p : -1e30f);
        sm += valid ? p : 0.f;
    }
    mx = fmaxf(mx, __shfl_xor_sync(0xffffffffu, mx, 8));
    sm += __shfl_xor_sync(0xffffffffu, sm, 8);
    mx = fmaxf(mx, __shfl_xor_sync(0xffffffffu, mx, 16));
    sm += __shfl_xor_sync(0xffffffffu, sm, 16);
    if (l == 0) g_M[bh * L + q] = mx - sm * (1.0f / (float)L);
}

// ---------------- top-38 per (b,h) ----------------
__global__ void k_topk() {
    int bh = blockIdx.x;
    __shared__ float vals[L];
    __shared__ float wv[8];
    __shared__ int   wi[8];
    int tid = threadIdx.x;
    int w = tid >> 5, lane = tid & 31;
    for (int i = tid; i < L; i += 256) vals[i] = g_M[bh * L + i];
    __syncthreads();
    for (int t = 0; t < NT; t++) {
        float bv = -1e38f; int bi = L;
        #pragma unroll
        for (int rep = 0; rep < L / 256; rep++) {
            int i = tid + rep * 256;
            float v = vals[i];
            if (v > bv || (v == bv && i < bi)) { bv = v; bi = i; }
        }
        #pragma unroll
        for (int off = 16; off; off >>= 1) {
            float ov = __shfl_down_sync(0xffffffffu, bv, off);
            int   oi = __shfl_down_sync(0xffffffffu, bi, off);
            if (ov > bv || (ov == bv && oi < bi)) { bv = ov; bi = oi; }
        }
        if (lane == 0) { wv[w] = bv; wi[w] = bi; }
        __syncthreads();
        if (tid == 0) {
            float fv = wv[0]; int fi = wi[0];
            #pragma unroll
            for (int ww = 1; ww < 8; ww++)
                if (wv[ww] > fv || (wv[ww] == fv && wi[ww] < fi)) { fv = wv[ww]; fi = wi[ww]; }
            g_top[bh * NT + t] = fi;
            vals[fi] = -1e38f;
        }
        __syncthreads();
    }
}

// ---------------- cumsum pass 1: per-chunk column sums ----------------
__global__ void k_csum_partial(const float* __restrict__ V) {
    int bh = blockIdx.x, chunk = blockIdx.y;
    int b = bh >> 3, h = bh & 7;
    int tid = threadIdx.x;
    int c = tid & 63, r0 = tid >> 6;
    float s = 0.f;
    for (int r = r0; r < CROWS; r += 4)
        s += V[(((size_t)b * L + chunk * CROWS + r) * H + h) * D + c];
    __shared__ float red[256];
    red[tid] = s;
    __syncthreads();
    if (tid < 64)
        g_csum[((size_t)bh * CH + chunk) * D + c] =
            red[tid] + red[tid + 64] + red[tid + 128] + red[tid + 192];
}

// ---------------- cumsum pass 2 ----------------
__global__ void k_csum_scan(const float* __restrict__ V, float* __restrict__ out) {
    int bh = blockIdx.x, chunk = blockIdx.y;
    int b = bh >> 3, h = bh & 7;
    __shared__ float tile[CROWS * 64];
    __shared__ float gsum[8 * 64];
    __shared__ float sbase[64];
    int tid = threadIdx.x;
    int c = tid & 63, g = tid >> 6;

    if (tid < 64) {
        float s = 0.f;
        for (int cc = 0; cc < chunk; cc++)
            s += g_csum[((size_t)bh * CH + cc) * D + tid];
        sbase[tid] = s;
    }
    int r0 = chunk * CROWS;
    for (int i = tid; i < CROWS * 64; i += 512) {
        int r = i >> 6, cc = i & 63;
        tile[i] = V[(((size_t)b * L + r0 + r) * H + h) * D + cc];
    }
    __syncthreads();

    float s = 0.f;
    int rb = g * 16;
    #pragma unroll
    for (int r = 0; r < 16; r++) {
        s += tile[(rb + r) * 64 + c];
        tile[(rb + r) * 64 + c] = s;
    }
    gsum[g * 64 + c] = s;
    __syncthreads();

    float prefix = sbase[c];
    for (int gg = 0; gg < g; gg++) prefix += gsum[gg * 64 + c];
    #pragma unroll
    for (int r = 0; r < 16; r++)
        out[(((size_t)b * L + r0 + rb + r) * H + h) * D + c] =
            tile[(rb + r) * 64 + c] + prefix;
}

// ---------------- attention split-K pass 1 ----------------
// Block (bh, chunk): K/V chunk of KC=64 keys staged in smem; each warp runs
// selected queries sidx = w, w+8, ... against the chunk. Deferred softmax:
// 8 scores per lane per 32-key half-chunk, one max/rescale per half-chunk.
// Lane layout: s = lane>>3 (key subgroup of 4), c = lane&7 (8-float dim chunk).
__global__ void k_attn_part(const float* __restrict__ Q, const float* __restrict__ K,
                            const float* __restrict__ V) {
    int bh = blockIdx.x, chunk = blockIdx.y;
    int b = bh >> 3, h = bh & 7;
    int c0 = chunk * KC;
    int tid = threadIdx.x;
    int w = tid >> 5, lane = tid & 31;
    int s = lane >> 3, c = lane & 7;

    __shared__ float4 sK[KC * 16];
    __shared__ float4 sV[KC * 16];
    const float4* K4 = (const float4*)K;
    const float4* V4 = (const float4*)V;
    for (int i = tid; i < KC * 16; i += 256) {
        int row = i >> 4, f = i & 15;
        size_t g = ((size_t)(b * L + c0 + row) * H + h) * 16 + f;
        sK[i] = K4[g];
        sV[i] = V4[g];
    }
    __syncthreads();

    const float scale = 0.125f;

    for (int t = 0; t < 5; t++) {
        int sidx = w + 8 * t;
        if (sidx >= NT) break;
        int q = g_top[bh * NT + sidx];
        int base = (bh * NT + sidx) * NC + chunk;
        if (q < c0) {
            if (lane == 0) { g_pm[base] = -1e30f; g_pl[base] = 0.f; }
            continue;
        }
        int nk = min(KC, q - c0 + 1);   // active keys in this chunk

        const float4* qr = (const float4*)(Q + (((size_t)b * L + q) * H + h) * D);
        float4 qa = qr[2 * c], qb = qr[2 * c + 1];

        float m = -1e30f, lsum = 0.f;
        float acc[8] = {0.f, 0.f, 0.f, 0.f, 0.f, 0.f, 0.f, 0.f};

        #pragma unroll
        for (int hc = 0; hc < 2; hc++) {
            if (hc * 32 >= nk) break;
            float sc[8];
            #pragma unroll
            for (int i = 0; i < 8; i++) {
                int kk = hc * 32 + i * 4 + s;
                float4 ka = sK[kk * 16 + 2 * c];
                float4 kb = sK[kk * 16 + 2 * c + 1];
                float p = ka.x * qa.x + ka.y * qa.y + ka.z * qa.z + ka.w * qa.w
                        + kb.x * qb.x + kb.y * qb.y + kb.z * qb.z + kb.w * qb.w;
                p += __shfl_xor_sync(0xffffffffu, p, 1);
                p += __shfl_xor_sync(0xffffffffu, p, 2);
                p += __shfl_xor_sync(0xffffffffu, p, 4);
                sc[i] = (kk < nk) ? p * scale : -1e30f;
            }
            float mloc = sc[0];
            #pragma unroll
            for (int i = 1; i < 8; i++) mloc = fmaxf(mloc, sc[i]);
            mloc = fmaxf(mloc, __shfl_xor_sync(0xffffffffu, mloc, 8));
            mloc = fmaxf(mloc, __shfl_xor_sync(0xffffffffu, mloc, 16));
            float mn = fmaxf(m, mloc);
            float alpha = __expf(m - mn);
            lsum *= alpha;
            #pragma unroll
            for (int d = 0; d < 8; d++) acc[d] *= alpha;
            #pragma unroll
            for (int i = 0; i < 8; i++) {
                int kk = hc * 32 + i * 4 + s;
                float pe = __expf(sc[i] - mn);   // masked -> exp(-huge) = 0
                lsum += pe;
                float4 va = sV[kk * 16 + 2 * c];
                float4 vb = sV[kk * 16 + 2 * c + 1];
                acc[0] += pe * va.x; acc[1] += pe * va.y;
                acc[2] += pe * va.z; acc[3] += pe * va.w;
                acc[4] += pe * vb.x; acc[5] += pe * vb.y;
                acc[6] += pe * vb.z; acc[7] += pe * vb.w;
            }
            m = mn;
        }

        // cross-group sum (m already uniform across groups)
        #pragma unroll
        for (int off = 8; off <= 16; off <<= 1) {
            lsum += __shfl_xor_sync(0xffffffffu, lsum, off);
            #pragma unroll
            for (int d = 0; d < 8; d++)
                acc[d] += __shfl_xor_sync(0xffffffffu, acc[d], off);
        }
        if (lane == 0) { g_pm[base] = m; g_pl[base] = lsum; }
        if (s == 0) {
            float* pa = &g_pacc[(size_t)base * D + c * 8];
            #pragma unroll
            for (int d = 0; d < 8; d++) pa[d] = acc[d];
        }
    }
}

// ---------------- attention merge: combine NC partials per selected query ----------------
__global__ void k_attn_merge(float* __restrict__ out) {
    int u = blockIdx.x;                 // (bh, sidx)
    int bh = u / NT, sidx = u % NT;
    int b = bh >> 3, h = bh & 7;
    int q = g_top[bh * NT + sidx];
    int d = threadIdx.x;                // 64 threads

    __shared__ float smm[NC], sll[NC];
    if (d < NC) {
        smm[d] = g_pm[u * NC + d];
        sll[d] = g_pl[u * NC + d];
    }
    __syncthreads();

    float gm = -1e30f;
    #pragma unroll
    for (int ch = 0; ch < NC; ch++)
        if (sll[ch] > 0.f) gm = fmaxf(gm, smm[ch]);
    float den = 0.f, num = 0.f;
    #pragma unroll 4
    for (int ch = 0; ch < NC; ch++) {
        if (sll[ch] > 0.f) {
            float f = __expf(smm[ch] - gm);
            den += f * sll[ch];
            num += f * g_pacc[((size_t)u * NC + ch) * D + d];
        }
    }
    out[(((size_t)b * L + q) * H + h) * D + d] = num / den;
}

// ---------------- launch ----------------
extern "C" void kernel_launch(void* const* d_in, const int* in_sizes, int n_in,
                              void* d_out, int out_size) {
    (void)in_sizes; (void)n_in; (void)out_size;
    const float* Q = (const float*)d_in[0];
    const float* K = (const float*)d_in[1];
    const float* V = (const float*)d_in[2];
    float* out = (float*)d_out;

    k_genidx<<<(NIDX + 255) / 256, 256>>>();
    k_M<<<dim3(B * H, L / 8), 256>>>(Q, K);
    k_topk<<<B * H, 256>>>();
    k_csum_partial<<<dim3(B * H, CH), 256>>>(V);
    k_csum_scan<<<dim3(B * H, CH), 512>>>(V, out);
    k_attn_part<<<dim3(B * H, NC), 256>>>(Q, K, V);
    k_attn_merge<<<B * H * NT, 64>>>(out);
}